// round 1
// baseline (speedup 1.0000x reference)
#include <cuda_runtime.h>

#define BB 64
#define CC 32
#define NN 1152
#define DI 8
#define DC 16
#define PP (CC*DC)          // 512 (c,i) pairs
#define NCHUNKS 32
#define NPC (NN/NCHUNKS)    // 36 n's per routing block

// Scratch (allocation-free: __device__ globals)
__device__ float g_hat[(size_t)BB*NN*PP];   // [B,N,C,DC]  151 MB
__device__ float g_s[3][BB*PP];             // s0,s1,s2
__device__ float g_out0[BB*PP];
__device__ float g_out1[BB*PP];
__device__ float g_dv2[BB*PP];              // out0+out1

// -------- zero the s accumulators (atomicAdd targets) --------
__global__ void zero_kernel() {
    int i = blockIdx.x * blockDim.x + threadIdx.x;
    if (i < 3*BB*PP) ((float*)g_s)[i] = 0.0f;
}

// -------- K1: inputs_hat[b,n,c,i] = sum_j W[c,n,i,j] * x[b,n,j] --------
// One block per n. W slice (512x8) and x slice (64x8) staged in smem.
__global__ __launch_bounds__(256) void hat_kernel(const float* __restrict__ x,
                                                  const float* __restrict__ W) {
    int n = blockIdx.x;
    int t = threadIdx.x;
    __shared__ float xs[BB*DI];     // 2 KB
    __shared__ float Ws[PP*DI];     // 16 KB

    for (int e = t; e < BB*DI; e += 256) {
        int b = e / DI, j = e % DI;
        xs[e] = x[(b*NN + n)*DI + j];
    }
    for (int e = t; e < PP*DI; e += 256) {
        int p = e / DI, j = e % DI;
        int c = p / DC, i = p % DC;
        Ws[e] = W[(((size_t)c*NN + n)*DC + i)*DI + j];
    }
    __syncthreads();

    int p0 = 2*t;
    float w0[DI], w1[DI];
#pragma unroll
    for (int j = 0; j < DI; j++) { w0[j] = Ws[p0*DI + j]; w1[j] = Ws[(p0+1)*DI + j]; }

    for (int b = 0; b < BB; b++) {
        float a0 = 0.f, a1 = 0.f;
#pragma unroll
        for (int j = 0; j < DI; j++) {
            float xv = xs[b*DI + j];
            a0 = fmaf(w0[j], xv, a0);
            a1 = fmaf(w1[j], xv, a1);
        }
        float2 v = make_float2(a0, a1);
        *reinterpret_cast<float2*>(&g_hat[((size_t)(b*NN + n))*PP + p0]) = v;
    }
}

// -------- fused routing pass --------
// MODE 0: uniform weights 1/32 (first iteration, softmax of zeros)
// MODE 1: logits[c,n] = dot_i(dv[b,c,:], hat[b,n,c,:]); softmax over c per n;
//         s[b,c,i] += w[c,n]*hat  (dv = out0 for iter1, out0+out1 for iter2)
template<int MODE>
__global__ __launch_bounds__(256) void route_kernel(const float* __restrict__ dv,
                                                    float* __restrict__ s) {
    int b = blockIdx.y;
    int t = threadIdx.x;
    __shared__ float dvs[PP];
    __shared__ float agr_s[CC];
    __shared__ float w_s[CC];

    float d0 = 0.f, d1 = 0.f;
    if (MODE == 1) {
        dvs[t]       = dv[b*PP + t];
        dvs[t + 256] = dv[b*PP + t + 256];
        __syncthreads();
        d0 = dvs[2*t]; d1 = dvs[2*t + 1];
    }

    int c = t >> 3;                   // pairs 2t,2t+1 live in capsule c = t/8
    float accx = 0.f, accy = 0.f;
    int nbase = blockIdx.x * NPC;
    const float2* hatp = reinterpret_cast<const float2*>(g_hat);

    for (int k = 0; k < NPC; k++) {
        int n = nbase + k;
        float2 h = hatp[((size_t)(b*NN + n))*(PP/2) + t];
        float w;
        if (MODE == 0) {
            w = 1.0f / CC;
        } else {
            // agreement dot over i: 8-lane tree within each capsule group
            float part = d0*h.x + d1*h.y;
            part += __shfl_down_sync(0xffffffffu, part, 4, 8);
            part += __shfl_down_sync(0xffffffffu, part, 2, 8);
            part += __shfl_down_sync(0xffffffffu, part, 1, 8);
            if ((t & 7) == 0) agr_s[c] = part;
            __syncthreads();
            // warp 0: softmax over 32 capsules
            if (t < 32) {
                float a = agr_s[t];
                float m = a;
#pragma unroll
                for (int o = 16; o > 0; o >>= 1) m = fmaxf(m, __shfl_xor_sync(0xffffffffu, m, o));
                float e = __expf(a - m);
                float es = e;
#pragma unroll
                for (int o = 16; o > 0; o >>= 1) es += __shfl_xor_sync(0xffffffffu, es, o);
                w_s[t] = e / es;
            }
            __syncthreads();
            w = w_s[c];
        }
        accx = fmaf(w, h.x, accx);
        accy = fmaf(w, h.y, accy);
    }
    atomicAdd(&s[b*PP + 2*t],     accx);
    atomicAdd(&s[b*PP + 2*t + 1], accy);
}

// -------- squash over DC=16 contiguous elements per (b,c) --------
__global__ __launch_bounds__(256) void squash_kernel(const float* __restrict__ s,
                                                     float* __restrict__ out,
                                                     const float* __restrict__ addv,
                                                     float* __restrict__ sumout) {
    int g = blockIdx.x * 256 + threadIdx.x;   // 0..32767
    float v = s[g];
    float sq = v*v;
#pragma unroll
    for (int o = 8; o > 0; o >>= 1) sq += __shfl_xor_sync(0xffffffffu, sq, o, 16);
    float scale = sq / (1.0f + sq) * rsqrtf(sq + 1e-7f);
    float o = scale * v;
    out[g] = o;
    if (addv) sumout[g] = o + addv[g];
}

extern "C" void kernel_launch(void* const* d_in, const int* in_sizes, int n_in,
                              void* d_out, int out_size) {
    const float* x = (const float*)d_in[0];
    const float* W = (const float*)d_in[1];
    if (in_sizes[0] != BB*NN*DI) { const float* tmp = x; x = W; W = tmp; }
    float* out = (float*)d_out;

    float *ss, *o0, *o1, *dv2;
    cudaGetSymbolAddress((void**)&ss,  g_s);
    cudaGetSymbolAddress((void**)&o0,  g_out0);
    cudaGetSymbolAddress((void**)&o1,  g_out1);
    cudaGetSymbolAddress((void**)&dv2, g_dv2);

    zero_kernel<<<(3*BB*PP + 255)/256, 256>>>();
    hat_kernel<<<NN, 256>>>(x, W);

    dim3 rg(NCHUNKS, BB);
    // iter 0: uniform weights -> s0 -> out0
    route_kernel<0><<<rg, 256>>>(nullptr, ss);
    squash_kernel<<<BB*PP/256, 256>>>(ss, o0, nullptr, nullptr);
    // iter 1: logits = agr(out0) -> s1 -> out1 ; also dv2 = out0+out1
    route_kernel<1><<<rg, 256>>>(o0, ss + BB*PP);
    squash_kernel<<<BB*PP/256, 256>>>(ss + BB*PP, o1, o0, dv2);
    // iter 2: logits = agr(out0)+agr(out1) = agr(out0+out1) -> s2 -> final out
    route_kernel<1><<<rg, 256>>>(dv2, ss + 2*BB*PP);
    squash_kernel<<<BB*PP/256, 256>>>(ss + 2*BB*PP, out, nullptr, nullptr);
}

// round 7
// speedup vs baseline: 2.1802x; 2.1802x over previous
#include <cuda_runtime.h>
#include <cuda_fp16.h>

#define BB 64
#define CC 32
#define NN 1152
#define DI 8
#define DC 16
#define PP 512            // C*DC
#define CH 16             // route n-chunks per b
#define NPW 9             // n per warp = NN/(CH*8)

// Scratch (allocation-free: __device__ globals)
__device__ __half g_hat[(size_t)BB*NN*PP];   // [B,N,C,DC] fp16, 75.5 MB (L2-resident)
__device__ float  g_s[3][BB*PP];             // s0,s1,s2 accumulators

// ---------------- hat: inputs_hat[b,n,c,i] = sum_j W[c,n,i,j]*x[b,n,j] ----------------
// One block per n. W slice (512x8) + x slice (64x8) staged in smem (float4).
__global__ __launch_bounds__(256) void hat_kernel(const float* __restrict__ x,
                                                  const float* __restrict__ W) {
    int n = blockIdx.x;
    int t = threadIdx.x;
    // fold s-accumulator zeroing into this kernel (blocks 0..2 each zero one buffer;
    // ordered before routing by the kernel-launch boundary)
    if (n < 3) {
        for (int e = t; e < BB*PP; e += 256) g_s[n][e] = 0.0f;
    }
    __shared__ float4 Ws4[1024];   // 16 KB: [p*2 + jhalf], p = c*16+i
    __shared__ float4 xs4[128];    // 2 KB:  [b*2 + jhalf]

    const float4* W4 = reinterpret_cast<const float4*>(W);
    const float4* x4 = reinterpret_cast<const float4*>(x);
#pragma unroll
    for (int f = t; f < 1024; f += 256) {
        int c = f >> 5, rem = f & 31;
        Ws4[f] = W4[(size_t)c*NN*32 + (size_t)n*32 + rem];
    }
    if (t < 128) {
        int b = t >> 1, hf = t & 1;
        xs4[t] = x4[(size_t)b*NN*2 + (size_t)n*2 + hf];
    }
    __syncthreads();

    // thread t owns pairs p0 = 2t, 2t+1 (fixed W in regs), loops over b
    float4 wa0 = Ws4[4*t+0], wb0 = Ws4[4*t+1];
    float4 wa1 = Ws4[4*t+2], wb1 = Ws4[4*t+3];
    __half2* hp = reinterpret_cast<__half2*>(g_hat);

#pragma unroll 4
    for (int b = 0; b < BB; b++) {
        float4 xa = xs4[2*b], xb = xs4[2*b+1];
        float a0 = fmaf(wa0.x, xa.x, fmaf(wa0.y, xa.y, fmaf(wa0.z, xa.z, wa0.w*xa.w)));
        a0 = fmaf(wb0.x, xb.x, fmaf(wb0.y, xb.y, fmaf(wb0.z, xb.z, fmaf(wb0.w, xb.w, a0))));
        float a1 = fmaf(wa1.x, xa.x, fmaf(wa1.y, xa.y, fmaf(wa1.z, xa.z, wa1.w*xa.w)));
        a1 = fmaf(wb1.x, xb.x, fmaf(wb1.y, xb.y, fmaf(wb1.z, xb.z, fmaf(wb1.w, xb.w, a1))));
        hp[((size_t)(b*NN + n))*256 + t] = __floats2half2_rn(a0, a1);
    }
}

// ---------------- helpers ----------------
__device__ __forceinline__ void unpack8(const uint4& u, float* h) {
    const __half2* p = reinterpret_cast<const __half2*>(&u);
#pragma unroll
    for (int k = 0; k < 4; k++) {
        float2 f = __half22float2(p[k]);
        h[2*k] = f.x; h[2*k+1] = f.y;
    }
}

__device__ __forceinline__ void squash16_add(const float* __restrict__ s, int off,
                                             float* dv, bool add) {
    const float4* p = reinterpret_cast<const float4*>(s + off);
    float v[16];
    float4 q0 = p[0], q1 = p[1], q2 = p[2], q3 = p[3];
    v[0]=q0.x; v[1]=q0.y; v[2]=q0.z; v[3]=q0.w;
    v[4]=q1.x; v[5]=q1.y; v[6]=q1.z; v[7]=q1.w;
    v[8]=q2.x; v[9]=q2.y; v[10]=q2.z; v[11]=q2.w;
    v[12]=q3.x; v[13]=q3.y; v[14]=q3.z; v[15]=q3.w;
    float sq = 0.f;
#pragma unroll
    for (int i = 0; i < 16; i++) sq = fmaf(v[i], v[i], sq);
    float sc = sq / (1.0f + sq) * rsqrtf(sq + 1e-7f);
#pragma unroll
    for (int i = 0; i < 16; i++) dv[i] = add ? fmaf(sc, v[i], dv[i]) : sc * v[i];
}

// ---------------- fused routing pass (warp-per-n, shfl softmax, no block barriers) ----
// MODE 0: uniform 1/32 weights (softmax of zero logits)
// MODE 1: dv = squash(sp0) [+ squash(sp1)]; logits = dv . hat; softmax over c; accumulate
template<int MODE>
__global__ __launch_bounds__(256) void route_kernel(const float* __restrict__ sp0,
                                                    const float* __restrict__ sp1,
                                                    float* __restrict__ sout) {
    int b = blockIdx.y;
    int w = threadIdx.x >> 5;     // warp id in block
    int c = threadIdx.x & 31;     // lane = output capsule

    float dv[16];
#pragma unroll
    for (int i = 0; i < 16; i++) dv[i] = 0.f;
    if (MODE == 1) {
        squash16_add(sp0, b*PP + c*DC, dv, false);
        if (sp1) squash16_add(sp1, b*PP + c*DC, dv, true);
    }

    float acc[16];
#pragma unroll
    for (int i = 0; i < 16; i++) acc[i] = 0.f;

    const uint4* hp = reinterpret_cast<const uint4*>(g_hat);
    int n0 = blockIdx.x * (8*NPW) + w * NPW;

#pragma unroll
    for (int k = 0; k < NPW; k++) {
        int n = n0 + k;
        size_t base = ((size_t)(b*NN + n)) * 64 + c*2;   // uint4 = 8 halves
        uint4 ua = hp[base];
        uint4 ub = hp[base + 1];
        float h[16];
        unpack8(ua, h);
        unpack8(ub, h + 8);
        float wgt;
        if (MODE == 0) {
            wgt = 1.0f / CC;
        } else {
            float d = 0.f;
#pragma unroll
            for (int i = 0; i < 16; i++) d = fmaf(dv[i], h[i], d);
            float m = d;
#pragma unroll
            for (int o = 16; o > 0; o >>= 1) m = fmaxf(m, __shfl_xor_sync(0xffffffffu, m, o));
            float e = __expf(d - m);
            float es = e;
#pragma unroll
            for (int o = 16; o > 0; o >>= 1) es += __shfl_xor_sync(0xffffffffu, es, o);
            wgt = e / es;
        }
#pragma unroll
        for (int i = 0; i < 16; i++) acc[i] = fmaf(wgt, h[i], acc[i]);
    }

    // block-level reduce (8 warps) then one atomicAdd set
    __shared__ float red[8*PP];   // 16 KB
    float4* rp = reinterpret_cast<float4*>(&red[w*PP + c*DC]);
    rp[0] = make_float4(acc[0], acc[1], acc[2], acc[3]);
    rp[1] = make_float4(acc[4], acc[5], acc[6], acc[7]);
    rp[2] = make_float4(acc[8], acc[9], acc[10], acc[11]);
    rp[3] = make_float4(acc[12], acc[13], acc[14], acc[15]);
    __syncthreads();

    int e0 = threadIdx.x * 2;
    float r0 = 0.f, r1 = 0.f;
#pragma unroll
    for (int ww = 0; ww < 8; ww++) {
        float2 v = *reinterpret_cast<float2*>(&red[ww*PP + e0]);
        r0 += v.x; r1 += v.y;
    }
    atomicAdd(&sout[b*PP + e0],     r0);
    atomicAdd(&sout[b*PP + e0 + 1], r1);
}

// ---------------- final squash -> output [B,C,DC] ----------------
__global__ __launch_bounds__(256) void squash_out_kernel(const float* __restrict__ s,
                                                         float* __restrict__ out) {
    int b = blockIdx.x * 8 + (threadIdx.x >> 5);
    int c = threadIdx.x & 31;
    float dv[16];
    squash16_add(s, b*PP + c*DC, dv, false);
    float4* op = reinterpret_cast<float4*>(out + b*PP + c*DC);
    op[0] = make_float4(dv[0], dv[1], dv[2], dv[3]);
    op[1] = make_float4(dv[4], dv[5], dv[6], dv[7]);
    op[2] = make_float4(dv[8], dv[9], dv[10], dv[11]);
    op[3] = make_float4(dv[12], dv[13], dv[14], dv[15]);
}

extern "C" void kernel_launch(void* const* d_in, const int* in_sizes, int n_in,
                              void* d_out, int out_size) {
    const float* x = (const float*)d_in[0];
    const float* W = (const float*)d_in[1];
    if (in_sizes[0] != BB*NN*DI) { const float* tmp = x; x = W; W = tmp; }
    float* out = (float*)d_out;

    float* ss;
    cudaGetSymbolAddress((void**)&ss, g_s);

    hat_kernel<<<NN, 256>>>(x, W);               // also zeroes s0,s1,s2

    dim3 rg(CH, BB);
    // iter 0: uniform weights -> s0
    route_kernel<0><<<rg, 256>>>(nullptr, nullptr, ss);
    // iter 1: dv = squash(s0) -> s1
    route_kernel<1><<<rg, 256>>>(ss, nullptr, ss + BB*PP);
    // iter 2: dv = squash(s0)+squash(s1)  (b-logit additivity) -> s2
    route_kernel<1><<<rg, 256>>>(ss, ss + BB*PP, ss + 2*BB*PP);
    // final: out = squash(s2)
    squash_out_kernel<<<BB/8, 256>>>(ss + 2*BB*PP, out);
}